// round 2
// baseline (speedup 1.0000x reference)
#include <cuda_runtime.h>

#define N_NODES   100000
#define N_EDGES   1600000
#define NFEAT     48
#define HIDDEN    256
#define TPB       256

// Scratch (device globals — no allocation allowed in kernel_launch)
__device__ float g_w[NFEAT];       // W1 @ W2  (48)
__device__ float g_cterm;          // bias[0]*sum(W2) + b2[0]
__device__ float g_deg[N_NODES];   // edge-count per destination (excl. self-loop)
__device__ float g_dinv[N_NODES];  // rsqrt(deg+1)
__device__ float g_y[N_NODES];     // x @ w
__device__ float g_z[N_NODES];     // dinv * y

// ---------------------------------------------------------------------------
// K0: block (gridDim.x-1) folds weights: w[f] = sum_h W1[f,h]*W2[h],
//     cterm = bias[0]*sum(W2)+b2[0].  All other blocks zero g_deg.
// ---------------------------------------------------------------------------
__global__ void k_prep(const float* __restrict__ W1,
                       const float* __restrict__ bias,
                       const float* __restrict__ W2,
                       const float* __restrict__ b2)
{
    if (blockIdx.x != gridDim.x - 1) {
        int i = blockIdx.x * TPB + threadIdx.x;
        if (i < N_NODES) g_deg[i] = 0.0f;
        return;
    }
    __shared__ float sW2[HIDDEN];
    __shared__ float sred[TPB];
    int t = threadIdx.x;
    sW2[t] = W2[t];
    __syncthreads();

    // block-reduce sum(W2) for the constant term
    sred[t] = sW2[t];
    __syncthreads();
    for (int s = TPB / 2; s > 0; s >>= 1) {
        if (t < s) sred[t] += sred[t + s];
        __syncthreads();
    }
    if (t == 0) g_cterm = bias[0] * sred[0] + b2[0];

    // 8 warps × 6 features each: warp-reduced 256-length dot products
    int warp = t >> 5, lane = t & 31;
    for (int f = warp; f < NFEAT; f += 8) {
        float p = 0.0f;
        for (int h = lane; h < HIDDEN; h += 32)
            p += W1[f * HIDDEN + h] * sW2[h];
        #pragma unroll
        for (int o = 16; o; o >>= 1)
            p += __shfl_down_sync(0xffffffffu, p, o);
        if (lane == 0) g_w[f] = p;
    }
}

// ---------------------------------------------------------------------------
// K1: degree histogram over edges + y[i] = x[i,:] . w  (grid sized for edges)
// ---------------------------------------------------------------------------
__global__ void k_deg_y(const float* __restrict__ x,
                        const int*   __restrict__ ei)
{
    __shared__ float sw[NFEAT];
    if (threadIdx.x < NFEAT) sw[threadIdx.x] = g_w[threadIdx.x];
    __syncthreads();

    int tid = blockIdx.x * TPB + threadIdx.x;
    if (tid < N_EDGES) {
        int c = ei[N_EDGES + tid];            // destination node
        atomicAdd(&g_deg[c], 1.0f);
    }
    if (tid < N_NODES) {
        const float4* xr = reinterpret_cast<const float4*>(x + (size_t)tid * NFEAT);
        float acc = 0.0f;
        #pragma unroll
        for (int j = 0; j < NFEAT / 4; j++) {
            float4 v = xr[j];
            acc += v.x * sw[4 * j + 0] + v.y * sw[4 * j + 1]
                 + v.z * sw[4 * j + 2] + v.w * sw[4 * j + 3];
        }
        g_y[tid] = acc;
    }
}

// ---------------------------------------------------------------------------
// K2: dinv, z = dinv*y, and self-loop + constant init of out
// ---------------------------------------------------------------------------
__global__ void k_init(float* __restrict__ out)
{
    int i = blockIdx.x * TPB + threadIdx.x;
    if (i >= N_NODES) return;
    float d = rsqrtf(g_deg[i] + 1.0f);        // deg includes self-loop => >= 1
    g_dinv[i] = d;
    float z = d * g_y[i];
    g_z[i] = z;
    out[i] = z * d + g_cterm;                 // y/deg + const
}

// ---------------------------------------------------------------------------
// K3: edge scatter: out[c] += dinv[r]*dinv[c]*y[r] = z[r]*dinv[c]
// ---------------------------------------------------------------------------
__global__ void k_edges(const int* __restrict__ ei,
                        float* __restrict__ out)
{
    int e = blockIdx.x * TPB + threadIdx.x;
    if (e >= N_EDGES) return;
    int r = ei[e];
    int c = ei[N_EDGES + e];
    float v = __ldg(&g_z[r]) * __ldg(&g_dinv[c]);
    atomicAdd(&out[c], v);
}

// ---------------------------------------------------------------------------
extern "C" void kernel_launch(void* const* d_in, const int* in_sizes, int n_in,
                              void* d_out, int out_size)
{
    const float* x    = (const float*)d_in[0];   // [N, 48]
    const int*   ei   = (const int*)  d_in[1];   // [2, E]
    const float* W1   = (const float*)d_in[2];   // [48, 256]
    const float* bias = (const float*)d_in[3];   // [1]
    const float* W2   = (const float*)d_in[4];   // [256, 1]
    const float* b2   = (const float*)d_in[5];   // [1]
    float* out = (float*)d_out;                  // [N, 1]

    const int node_blocks = (N_NODES + TPB - 1) / TPB;   // 391
    const int edge_blocks = (N_EDGES + TPB - 1) / TPB;   // 6250

    k_prep <<<node_blocks + 1, TPB>>>(W1, bias, W2, b2);
    k_deg_y<<<edge_blocks,     TPB>>>(x, ei);
    k_init <<<node_blocks,     TPB>>>(out);
    k_edges<<<edge_blocks,     TPB>>>(ei, out);
}

// round 3
// speedup vs baseline: 1.4169x; 1.4169x over previous
#include <cuda_runtime.h>

#define N_NODES   100000
#define N_EDGES   1600000
#define NFEAT     48
#define HIDDEN    256
#define TPB       256
#define EPT       4                      // edges per thread (int4)

// Scratch (device globals — no allocation allowed in kernel_launch)
__device__ float g_w[NFEAT];       // W1 @ W2  (48)
__device__ float g_cterm;          // bias[0]*sum(W2) + b2[0]
__device__ float g_deg[N_NODES];   // edge-count per destination (excl. self-loop)
__device__ float g_dinv[N_NODES];  // rsqrt(deg+1)
__device__ float g_y[N_NODES];     // x @ w
__device__ float g_s[N_NODES];     // z[c] + sum_{r->c} z[r]   (z = dinv*y)

// ---------------------------------------------------------------------------
// K0: block (gridDim.x-1) folds weights: w[f] = sum_h W1[f,h]*W2[h],
//     cterm = bias[0]*sum(W2)+b2[0].  All other blocks zero g_deg.
// ---------------------------------------------------------------------------
__global__ void k_prep(const float* __restrict__ W1,
                       const float* __restrict__ bias,
                       const float* __restrict__ W2,
                       const float* __restrict__ b2)
{
    if (blockIdx.x != gridDim.x - 1) {
        int i = blockIdx.x * TPB + threadIdx.x;
        if (i < N_NODES) g_deg[i] = 0.0f;
        return;
    }
    __shared__ float sW2[HIDDEN];
    __shared__ float sred[TPB];
    int t = threadIdx.x;
    sW2[t] = W2[t];
    __syncthreads();

    sred[t] = sW2[t];
    __syncthreads();
    for (int s = TPB / 2; s > 0; s >>= 1) {
        if (t < s) sred[t] += sred[t + s];
        __syncthreads();
    }
    if (t == 0) g_cterm = bias[0] * sred[0] + b2[0];

    int warp = t >> 5, lane = t & 31;
    for (int f = warp; f < NFEAT; f += 8) {
        float p = 0.0f;
        for (int h = lane; h < HIDDEN; h += 32)
            p += W1[f * HIDDEN + h] * sW2[h];
        #pragma unroll
        for (int o = 16; o; o >>= 1)
            p += __shfl_down_sync(0xffffffffu, p, o);
        if (lane == 0) g_w[f] = p;
    }
}

// ---------------------------------------------------------------------------
// K1: degree histogram over edges (int4, 4 edges/thread) + y[i] = x[i,:].w
// ---------------------------------------------------------------------------
__global__ void k_deg_y(const float* __restrict__ x,
                        const int*   __restrict__ ei)
{
    __shared__ float sw[NFEAT];
    if (threadIdx.x < NFEAT) sw[threadIdx.x] = g_w[threadIdx.x];
    __syncthreads();

    int tid = blockIdx.x * TPB + threadIdx.x;

    // degree: 4 destination indices per thread via one LDG.128
    if (tid < N_EDGES / EPT) {
        int4 c4 = reinterpret_cast<const int4*>(ei + N_EDGES)[tid];
        atomicAdd(&g_deg[c4.x], 1.0f);
        atomicAdd(&g_deg[c4.y], 1.0f);
        atomicAdd(&g_deg[c4.z], 1.0f);
        atomicAdd(&g_deg[c4.w], 1.0f);
    }
    // node dot product (first 391 blocks' worth of threads)
    if (tid < N_NODES) {
        const float4* xr = reinterpret_cast<const float4*>(x + (size_t)tid * NFEAT);
        float acc = 0.0f;
        #pragma unroll
        for (int j = 0; j < NFEAT / 4; j++) {
            float4 v = xr[j];
            acc += v.x * sw[4 * j + 0] + v.y * sw[4 * j + 1]
                 + v.z * sw[4 * j + 2] + v.w * sw[4 * j + 3];
        }
        g_y[tid] = acc;
    }
}

// ---------------------------------------------------------------------------
// K2: dinv = rsqrt(deg+1);  s = z = dinv*y  (self-loop seed)
// ---------------------------------------------------------------------------
__global__ void k_init()
{
    int i = blockIdx.x * TPB + threadIdx.x;
    if (i >= N_NODES) return;
    float d = rsqrtf(g_deg[i] + 1.0f);
    g_dinv[i] = d;
    g_s[i] = d * g_y[i];                  // z[i]; self-loop contribution seed
}

// ---------------------------------------------------------------------------
// K3: edge scatter: s[c] += z[r]    (z read from g_s BEFORE any add lands?
//     NO — g_s is being mutated. Need a separate z array? z[r] must be the
//     pre-scatter value. Keep z in g_y's slot? g_y is free after k_init if we
//     fold z into it: store z into g_y in k_init, seed g_s with z too.)
// ---------------------------------------------------------------------------
__global__ void k_edges(const int* __restrict__ ei)
{
    int tid = blockIdx.x * TPB + threadIdx.x;
    if (tid >= N_EDGES / EPT) return;
    int4 r4 = reinterpret_cast<const int4*>(ei)[tid];
    int4 c4 = reinterpret_cast<const int4*>(ei + N_EDGES)[tid];
    // g_y holds z (written by k_init2 below); g_s is the accumulator
    float z0 = __ldg(&g_y[r4.x]);
    float z1 = __ldg(&g_y[r4.y]);
    float z2 = __ldg(&g_y[r4.z]);
    float z3 = __ldg(&g_y[r4.w]);
    atomicAdd(&g_s[c4.x], z0);
    atomicAdd(&g_s[c4.y], z1);
    atomicAdd(&g_s[c4.z], z2);
    atomicAdd(&g_s[c4.w], z3);
}

// ---------------------------------------------------------------------------
// K4: out[c] = dinv[c]*s[c] + cterm
// ---------------------------------------------------------------------------
__global__ void k_final(float* __restrict__ out)
{
    int i = blockIdx.x * TPB + threadIdx.x;
    if (i >= N_NODES) return;
    out[i] = g_dinv[i] * g_s[i] + g_cterm;
}

// K2 variant that writes z into g_y (overwriting y — safe, y only feeds z)
__global__ void k_init2()
{
    int i = blockIdx.x * TPB + threadIdx.x;
    if (i >= N_NODES) return;
    float d = rsqrtf(g_deg[i] + 1.0f);
    float z = d * g_y[i];
    g_dinv[i] = d;
    g_y[i]    = z;     // z, gathered by k_edges
    g_s[i]    = z;     // accumulator seeded with self-loop term
}

// ---------------------------------------------------------------------------
extern "C" void kernel_launch(void* const* d_in, const int* in_sizes, int n_in,
                              void* d_out, int out_size)
{
    const float* x    = (const float*)d_in[0];   // [N, 48]
    const int*   ei   = (const int*)  d_in[1];   // [2, E]
    const float* W1   = (const float*)d_in[2];   // [48, 256]
    const float* bias = (const float*)d_in[3];   // [1]
    const float* W2   = (const float*)d_in[4];   // [256, 1]
    const float* b2   = (const float*)d_in[5];   // [1]
    float* out = (float*)d_out;                  // [N, 1]

    const int node_blocks  = (N_NODES + TPB - 1) / TPB;            // 391
    const int edge4_blocks = (N_EDGES / EPT + TPB - 1) / TPB;      // 1563

    k_prep  <<<node_blocks + 1, TPB>>>(W1, bias, W2, b2);
    k_deg_y <<<edge4_blocks > node_blocks ? edge4_blocks : node_blocks, TPB>>>(x, ei);
    k_init2 <<<node_blocks,  TPB>>>();
    k_edges <<<edge4_blocks, TPB>>>(ei);
    k_final <<<node_blocks,  TPB>>>(out);
}

// round 4
// speedup vs baseline: 1.4261x; 1.0065x over previous
#include <cuda_runtime.h>

#define N_NODES   100000
#define N_EDGES   1600000
#define NFEAT     48
#define HIDDEN    256
#define TPB       256
#define EPT       8                       // edges per thread (2x int4)
#define EDGE_THREADS (N_EDGES / EPT)      // 200000
#define EDGE_BLOCKS  ((EDGE_THREADS + TPB - 1) / TPB)   // 782
#define NODE_BLOCKS  ((N_NODES + TPB - 1) / TPB)        // 391

// Scratch (device globals — zero-initialized at module load; g_deg is
// restored to all-zeros by k_final at the end of EVERY call, so each call
// observes the identical starting state: deterministic.)
__device__ float g_w[NFEAT];       // W1 @ W2  (48)
__device__ float g_cterm;          // bias[0]*sum(W2) + b2[0]
__device__ float g_deg[N_NODES];   // per-destination edge count (zeroed by k_final)
__device__ float g_dinv[N_NODES];  // rsqrt(deg+1)
__device__ float g_z[N_NODES];     // dinv * (x @ w)
__device__ float g_s[N_NODES];     // z[c] + sum_{r->c} z[r]

// ---------------------------------------------------------------------------
// K1: degree histogram over edges (8 edges/thread). Last block instead folds
//     the weights: w[f] = sum_h W1[f,h]*W2[h], cterm = bias[0]*sum(W2)+b2[0].
// ---------------------------------------------------------------------------
__global__ void __launch_bounds__(TPB) k_deg(const int* __restrict__ ei,
                                             const float* __restrict__ W1,
                                             const float* __restrict__ bias,
                                             const float* __restrict__ W2,
                                             const float* __restrict__ b2)
{
    if (blockIdx.x == gridDim.x - 1) {
        __shared__ float sW2[HIDDEN];
        __shared__ float sred[TPB];
        int t = threadIdx.x;
        sW2[t] = W2[t];
        __syncthreads();

        sred[t] = sW2[t];
        __syncthreads();
        for (int s = TPB / 2; s > 0; s >>= 1) {
            if (t < s) sred[t] += sred[t + s];
            __syncthreads();
        }
        if (t == 0) g_cterm = bias[0] * sred[0] + b2[0];

        int warp = t >> 5, lane = t & 31;
        for (int f = warp; f < NFEAT; f += 8) {
            float p = 0.0f;
            for (int h = lane; h < HIDDEN; h += 32)
                p += W1[f * HIDDEN + h] * sW2[h];
            #pragma unroll
            for (int o = 16; o; o >>= 1)
                p += __shfl_down_sync(0xffffffffu, p, o);
            if (lane == 0) g_w[f] = p;
        }
        return;
    }

    int tid = blockIdx.x * TPB + threadIdx.x;
    if (tid >= EDGE_THREADS) return;
    const int4* cols = reinterpret_cast<const int4*>(ei + N_EDGES);
    int4 a = cols[2 * tid + 0];
    int4 b = cols[2 * tid + 1];
    atomicAdd(&g_deg[a.x], 1.0f);
    atomicAdd(&g_deg[a.y], 1.0f);
    atomicAdd(&g_deg[a.z], 1.0f);
    atomicAdd(&g_deg[a.w], 1.0f);
    atomicAdd(&g_deg[b.x], 1.0f);
    atomicAdd(&g_deg[b.y], 1.0f);
    atomicAdd(&g_deg[b.z], 1.0f);
    atomicAdd(&g_deg[b.w], 1.0f);
}

// ---------------------------------------------------------------------------
// K2: node init: y = x.w ; dinv = rsqrt(deg+1) ; z = dinv*y ;
//     s seeded with z (self-loop term).
// ---------------------------------------------------------------------------
__global__ void __launch_bounds__(TPB) k_init(const float* __restrict__ x)
{
    __shared__ float sw[NFEAT];
    if (threadIdx.x < NFEAT) sw[threadIdx.x] = g_w[threadIdx.x];
    __syncthreads();

    int i = blockIdx.x * TPB + threadIdx.x;
    if (i >= N_NODES) return;

    const float4* xr = reinterpret_cast<const float4*>(x + (size_t)i * NFEAT);
    float acc = 0.0f;
    #pragma unroll
    for (int j = 0; j < NFEAT / 4; j++) {
        float4 v = xr[j];
        acc += v.x * sw[4 * j + 0] + v.y * sw[4 * j + 1]
             + v.z * sw[4 * j + 2] + v.w * sw[4 * j + 3];
    }
    float d = rsqrtf(g_deg[i] + 1.0f);    // +1 = self-loop
    float z = d * acc;
    g_dinv[i] = d;
    g_z[i]    = z;
    g_s[i]    = z;                        // accumulator seeded w/ self-loop term
}

// ---------------------------------------------------------------------------
// K3: edge scatter: s[c] += z[r]   (8 edges/thread)
// ---------------------------------------------------------------------------
__global__ void __launch_bounds__(TPB) k_edges(const int* __restrict__ ei)
{
    int tid = blockIdx.x * TPB + threadIdx.x;
    if (tid >= EDGE_THREADS) return;
    const int4* rows = reinterpret_cast<const int4*>(ei);
    const int4* cols = reinterpret_cast<const int4*>(ei + N_EDGES);
    int4 r0 = rows[2 * tid + 0];
    int4 r1 = rows[2 * tid + 1];
    int4 c0 = cols[2 * tid + 0];
    int4 c1 = cols[2 * tid + 1];

    float z0 = __ldg(&g_z[r0.x]);
    float z1 = __ldg(&g_z[r0.y]);
    float z2 = __ldg(&g_z[r0.z]);
    float z3 = __ldg(&g_z[r0.w]);
    float z4 = __ldg(&g_z[r1.x]);
    float z5 = __ldg(&g_z[r1.y]);
    float z6 = __ldg(&g_z[r1.z]);
    float z7 = __ldg(&g_z[r1.w]);

    atomicAdd(&g_s[c0.x], z0);
    atomicAdd(&g_s[c0.y], z1);
    atomicAdd(&g_s[c0.z], z2);
    atomicAdd(&g_s[c0.w], z3);
    atomicAdd(&g_s[c1.x], z4);
    atomicAdd(&g_s[c1.y], z5);
    atomicAdd(&g_s[c1.z], z6);
    atomicAdd(&g_s[c1.w], z7);
}

// ---------------------------------------------------------------------------
// K4: out = dinv*s + cterm ; reset g_deg to 0 for the next call (invariant:
//     g_deg is all-zeros at entry and exit of every kernel_launch call).
// ---------------------------------------------------------------------------
__global__ void __launch_bounds__(TPB) k_final(float* __restrict__ out)
{
    int i = blockIdx.x * TPB + threadIdx.x;
    if (i >= N_NODES) return;
    out[i] = g_dinv[i] * g_s[i] + g_cterm;
    g_deg[i] = 0.0f;
}

// ---------------------------------------------------------------------------
extern "C" void kernel_launch(void* const* d_in, const int* in_sizes, int n_in,
                              void* d_out, int out_size)
{
    const float* x    = (const float*)d_in[0];   // [N, 48]
    const int*   ei   = (const int*)  d_in[1];   // [2, E]
    const float* W1   = (const float*)d_in[2];   // [48, 256]
    const float* bias = (const float*)d_in[3];   // [1]
    const float* W2   = (const float*)d_in[4];   // [256, 1]
    const float* b2   = (const float*)d_in[5];   // [1]
    float* out = (float*)d_out;                  // [N, 1]

    k_deg   <<<EDGE_BLOCKS + 1, TPB>>>(ei, W1, bias, W2, b2);
    k_init  <<<NODE_BLOCKS,     TPB>>>(x);
    k_edges <<<EDGE_BLOCKS,     TPB>>>(ei);
    k_final <<<NODE_BLOCKS,     TPB>>>(out);
}